// round 1
// baseline (speedup 1.0000x reference)
#include <cuda_runtime.h>
#include <stdint.h>

#define N_BCH 8
#define N_ATM 10000
#define N_ELM 100
#define THREADS 256
#define GRID_MAIN 1184   // 8 CTAs/SM * 148 SMs

// Scratch (no cudaMalloc allowed): element-type table as u8 (80 KB, L1-resident)
// and packed (k, radius) per element type.
__device__ uint8_t g_elm8[N_BCH * N_ATM];
__device__ float2  g_kr[N_ELM];

// ---------------------------------------------------------------------------
// Prepass: zero the 8 outputs, pack k/radius, convert elm int32 -> uint8.
// ---------------------------------------------------------------------------
__global__ void prep_kernel(const int* __restrict__ elm,
                            const float* __restrict__ k,
                            const float* __restrict__ radius,
                            float* __restrict__ out)
{
    int tid = blockIdx.x * blockDim.x + threadIdx.x;
    if (tid < N_BCH) out[tid] = 0.0f;
    if (tid < N_ELM) g_kr[tid] = make_float2(k[tid], radius[tid]);
    for (int i = tid; i < N_BCH * N_ATM; i += gridDim.x * blockDim.x)
        g_elm8[i] = (uint8_t)elm[i];
}

// ---------------------------------------------------------------------------
// Main: stream edges (vectorized 16B loads), gather u8 element types (L1),
// accumulate into per-thread shared-memory bins, block-reduce, 8 atomics.
// ---------------------------------------------------------------------------
__device__ __forceinline__ void edge_op(int n, int i, int j, float s,
                                        float* __restrict__ acc_col)
{
    const float2* __restrict__ kr = g_kr;
    int a = g_elm8[n * N_ATM + i];
    int b = g_elm8[n * N_ATM + j];
    float2 ka = __ldg(&kr[a]);
    float2 kb = __ldg(&kr[b]);
    float dis = sqrtf(s);
    float R   = ka.y + kb.y;
    if (dis < R) {
        float d = dis - R;
        acc_col[n * THREADS] += (ka.x + kb.x) * d * d;
    }
}

__global__ void __launch_bounds__(THREADS)
close_penalty_kernel(const int4*  __restrict__ edge_n4,
                     const int4*  __restrict__ edge_i4,
                     const int4*  __restrict__ edge_j4,
                     const float4* __restrict__ sod4,
                     const int*   __restrict__ edge_n,
                     const int*   __restrict__ edge_i,
                     const int*   __restrict__ edge_j,
                     const float* __restrict__ sod,
                     float* __restrict__ out,
                     int nvec, int E)
{
    __shared__ float acc[N_BCH * THREADS];
    float* acc_col = &acc[threadIdx.x];
    #pragma unroll
    for (int b = 0; b < N_BCH; b++) acc_col[b * THREADS] = 0.0f;

    int gtid   = blockIdx.x * blockDim.x + threadIdx.x;
    int stride = gridDim.x * blockDim.x;

    for (int v = gtid; v < nvec; v += stride) {
        int4   en = edge_n4[v];
        int4   ei = edge_i4[v];
        int4   ej = edge_j4[v];
        float4 s  = sod4[v];
        edge_op(en.x, ei.x, ej.x, s.x, acc_col);
        edge_op(en.y, ei.y, ej.y, s.y, acc_col);
        edge_op(en.z, ei.z, ej.z, s.z, acc_col);
        edge_op(en.w, ei.w, ej.w, s.w, acc_col);
    }

    // Scalar tail (E not multiple of 4) — handled by first few global threads.
    int tail_base = nvec * 4;
    int t = tail_base + gtid;
    if (t < E) edge_op(edge_n[t], edge_i[t], edge_j[t], sod[t], acc_col);

    __syncthreads();

    // Block tree-reduction over the 256 columns, all 8 bins in parallel.
    #pragma unroll
    for (int s = THREADS / 2; s > 0; s >>= 1) {
        if (threadIdx.x < s) {
            #pragma unroll
            for (int b = 0; b < N_BCH; b++)
                acc[b * THREADS + threadIdx.x] += acc[b * THREADS + threadIdx.x + s];
        }
        __syncthreads();
    }

    if (threadIdx.x < N_BCH)
        atomicAdd(&out[threadIdx.x], acc[threadIdx.x * THREADS]);
}

// ---------------------------------------------------------------------------
// Launch
// ---------------------------------------------------------------------------
extern "C" void kernel_launch(void* const* d_in, const int* in_sizes, int n_in,
                              void* d_out, int out_size)
{
    const int*   elm    = (const int*)  d_in[0];
    const int*   edge_n = (const int*)  d_in[1];
    const int*   edge_i = (const int*)  d_in[2];
    const int*   edge_j = (const int*)  d_in[3];
    const float* sod    = (const float*)d_in[4];
    const float* k      = (const float*)d_in[5];
    const float* radius = (const float*)d_in[6];
    float* out = (float*)d_out;

    int E    = in_sizes[1];
    int nvec = E >> 2;

    prep_kernel<<<(N_BCH * N_ATM + 255) / 256, 256>>>(elm, k, radius, out);

    int grid = GRID_MAIN;
    int need = (nvec + THREADS - 1) / THREADS;
    if (need < grid) grid = need > 0 ? need : 1;

    close_penalty_kernel<<<grid, THREADS>>>(
        (const int4*)edge_n, (const int4*)edge_i, (const int4*)edge_j,
        (const float4*)sod,
        edge_n, edge_i, edge_j, sod,
        out, nvec, E);
}